// round 4
// baseline (speedup 1.0000x reference)
#include <cuda_runtime.h>
#include <cuda_bf16.h>

// GraphAttention via CSR gather (no value-scatter atomics).
// Inputs (metadata order): q0[N,32,1] q1[N,32,3] k0[E,32,1] k1[E,32,3]
//                          v0[E,32,1] v1[E,32,3] edge_dst[E] (int32 or int64)
// Output: concat(out0[N,32], out1[N,96]) float32, N*128 elements.
//
// R3 post-mortem: REDG costs ~1 cyc/LANE at the LSU; scattering 32 red-lanes
// per edge is ~100us of issue time alone. So: bin edges by dst (cheap), then
// warp-per-node gathers its edges, accumulates value+denominator in registers,
// and stores the output once. Zero atomics on the value path.

#define N_NODES_MAX 50016
#define E_MAX_C     800000
#define N_HEADS_C   8

__device__ int g_count [N_NODES_MAX];   // edges per node
__device__ int g_start [N_NODES_MAX];   // exclusive prefix (CSR row start)
__device__ int g_cursor[N_NODES_MAX];   // mutable copy for bucket fill
__device__ int g_bucket[E_MAX_C];       // edge ids grouped by dst

// JAX with x64 disabled hands us int32 even though the reference asked for
// int64. Sniff dtype: for int64 the odd 32-bit words (high halves of indices
// < 50000) are all zero; for random int32 indices P(all four zero) ~ 0.
__device__ __forceinline__ int load_dst(const int* __restrict__ dst32, int e) {
    bool is64 = (dst32[1] == 0) & (dst32[3] == 0) & (dst32[5] == 0) & (dst32[7] == 0);
    return is64 ? dst32[2 * e] : dst32[e];
}

__global__ void __launch_bounds__(256) hist_kernel(
    const int* __restrict__ edge_dst, int E)
{
    int e = blockIdx.x * blockDim.x + threadIdx.x;
    if (e >= E) return;
    atomicAdd(&g_count[load_dst(edge_dst, e)], 1);
}

// Single-block exclusive scan of g_count -> g_start/g_cursor.
__global__ void __launch_bounds__(1024) scan_kernel(int n)
{
    __shared__ int partials[1024];
    int t = threadIdx.x;
    int ch = (n + 1023) / 1024;
    int base = t * ch;
    int s = 0;
    for (int i = 0; i < ch; i++) {
        int idx = base + i;
        if (idx < n) s += g_count[idx];
    }
    partials[t] = s;
    __syncthreads();
    // Hillis-Steele inclusive scan over 1024 partials.
    for (int off = 1; off < 1024; off <<= 1) {
        int v = (t >= off) ? partials[t - off] : 0;
        __syncthreads();
        partials[t] += v;
        __syncthreads();
    }
    int run = partials[t] - s;   // exclusive base for this chunk
    for (int i = 0; i < ch; i++) {
        int idx = base + i;
        if (idx < n) {
            g_start[idx]  = run;
            g_cursor[idx] = run;
            run += g_count[idx];
        }
    }
}

__global__ void __launch_bounds__(256) bin_kernel(
    const int* __restrict__ edge_dst, int E)
{
    int e = blockIdx.x * blockDim.x + threadIdx.x;
    if (e >= E) return;
    int d = load_dst(edge_dst, e);
    int slot = atomicAdd(&g_cursor[d], 1);
    g_bucket[slot] = e;
}

// One warp per node. Lane mapping over the 32 float4s of the concatenated
// feature vector:
//   lane 0..7   -> deg-0 float4 #lane     (head = lane)
//   lane 8..31  -> deg-1 float4 #(lane-8) (head = (lane-8)/3)
// q float4 lives in registers for the whole edge loop. Per edge: load k,
// shuffle-assemble the 8 head scores, exp, accumulate denom + ex*v in regs.
__global__ void __launch_bounds__(256) ga_gather_kernel(
    const float4* __restrict__ k0, const float4* __restrict__ k1,
    const float4* __restrict__ q0, const float4* __restrict__ q1,
    const float4* __restrict__ v0, const float4* __restrict__ v1,
    float* __restrict__ out,
    int n_nodes)
{
    int warp_id = (blockIdx.x * blockDim.x + threadIdx.x) >> 5;
    if (warp_id >= n_nodes) return;
    int lane = threadIdx.x & 31;
    int n = warp_id;

    bool lo = lane < 8;
    int j = lane - 8;            // deg-1 float4 index (valid when !lo)
    int h = lo ? lane : j / 3;   // head owning this lane's float4

    float4 qv = lo ? q0[n * 8 + lane] : q1[n * 24 + j];

    int start = g_start[n];
    int cnt   = g_count[n];

    float4 acc = make_float4(0.f, 0.f, 0.f, 0.f);
    float den = 0.f;
    const unsigned m = 0xffffffffu;

#pragma unroll 2
    for (int i = 0; i < cnt; i++) {
        int e = g_bucket[start + i];
        float4 kv = lo ? k0[e * 8 + lane] : k1[e * 24 + j];
        float p = kv.x * qv.x + kv.y * qv.y + kv.z * qv.z + kv.w * qv.w;
        float s = __shfl_sync(m, p, h)
                + __shfl_sync(m, p, 8 + 3 * h)
                + __shfl_sync(m, p, 9 + 3 * h)
                + __shfl_sync(m, p, 10 + 3 * h);
        // score / sqrt(128); shift-free softmax is safe (|score| < ~3).
        float ex = __expf(s * 0.08838834764831845f);
        den += ex;
        float4 vv = lo ? v0[e * 8 + lane] : v1[e * 24 + j];
        acc.x += ex * vv.x;
        acc.y += ex * vv.y;
        acc.z += ex * vv.z;
        acc.w += ex * vv.w;
    }

    float inv = (cnt > 0) ? (1.0f / den) : 0.0f;
    acc.x *= inv; acc.y *= inv; acc.z *= inv; acc.w *= inv;

    float* o = lo ? (out + (size_t)n * 32 + lane * 4)
                  : (out + (size_t)n_nodes * 32 + (size_t)n * 96 + j * 4);
    *(float4*)o = acc;
}

extern "C" void kernel_launch(void* const* d_in, const int* in_sizes, int n_in,
                              void* d_out, int out_size)
{
    const float4* q0 = (const float4*)d_in[0];
    const float4* q1 = (const float4*)d_in[1];
    const float4* k0 = (const float4*)d_in[2];
    const float4* k1 = (const float4*)d_in[3];
    const float4* v0 = (const float4*)d_in[4];
    const float4* v1 = (const float4*)d_in[5];
    const int* edge_dst = (const int*)d_in[6];
    float* out = (float*)d_out;

    int E = in_sizes[2] / 32;          // k0 has E*32 elements
    int n_nodes = out_size / 128;      // 32 + 96 floats per node

    void* cnt_ptr = nullptr;
    cudaGetSymbolAddress(&cnt_ptr, g_count);
    cudaMemsetAsync(cnt_ptr, 0, (size_t)n_nodes * sizeof(int));

    int eb = (E + 255) / 256;
    hist_kernel<<<eb, 256>>>(edge_dst, E);
    scan_kernel<<<1, 1024>>>(n_nodes);
    bin_kernel<<<eb, 256>>>(edge_dst, E);

    int threads = n_nodes * 32;
    ga_gather_kernel<<<(threads + 255) / 256, 256>>>(
        k0, k1, q0, q1, v0, v1, out, n_nodes);
}

// round 5
// speedup vs baseline: 1.1886x; 1.1886x over previous
#include <cuda_runtime.h>
#include <cuda_bf16.h>

// GraphAttention, 3-phase: (1) streaming score pass writes exp(score) per
// (edge,head) and histograms degrees; (2) scan+bin builds CSR; (3) warp-per-
// node gather accumulates ex*v and the per-head denominator in registers.
// No value-scatter atomics (R3: REDG ~1 cyc/LANE made scatter ~100us of LSU
// issue), no long dependency chains (R4: fused gather was latency-bound).
//
// Inputs (metadata order): q0[N,32,1] q1[N,32,3] k0[E,32,1] k1[E,32,3]
//                          v0[E,32,1] v1[E,32,3] edge_dst[E] (int32 or int64)
// Output: concat(out0[N,32], out1[N,96]) float32, N*128 elements.

#define N_NODES_MAX 50016
#define E_MAX_C     800000
#define N_HEADS_C   8

__device__ float g_ex   [E_MAX_C * N_HEADS_C];
__device__ int   g_count [N_NODES_MAX];
__device__ int   g_start [N_NODES_MAX];
__device__ int   g_cursor[N_NODES_MAX];
__device__ int   g_bucket[E_MAX_C];

// JAX with x64 disabled hands us int32 even though the reference asked for
// int64. Sniff dtype: for int64 the odd 32-bit words (high halves of indices
// < 50000) are all zero; for random int32 indices P(all four zero) ~ 0.
__device__ __forceinline__ int load_dst(const int* __restrict__ dst32, int e) {
    bool is64 = (dst32[1] == 0) & (dst32[3] == 0) & (dst32[5] == 0) & (dst32[7] == 0);
    return is64 ? dst32[2 * e] : dst32[e];
}

// Phase 1: thread per (edge, head). Coalesced k stream, L2-resident q gather,
// 16 FMAs, exp, coalesced ex store. h==0 thread also histograms the degree.
__global__ void __launch_bounds__(256) ga_score_kernel(
    const float4* __restrict__ k0,   // [E*8]  float4 view of [E,32]
    const float4* __restrict__ k1,   // [E*24] float4 view of [E,96]
    const float4* __restrict__ q0,   // [N*8]
    const float4* __restrict__ q1,   // [N*24]
    const int* __restrict__ edge_dst,
    int E)
{
    int tid = blockIdx.x * blockDim.x + threadIdx.x;
    if (tid >= E * N_HEADS_C) return;
    int e = tid >> 3;
    int h = tid & 7;
    int d = load_dst(edge_dst, e);

    float4 a0 = k0[e * 8 + h];
    float4 b0 = q0[d * 8 + h];
    float acc = a0.x * b0.x + a0.y * b0.y + a0.z * b0.z + a0.w * b0.w;
#pragma unroll
    for (int i = 0; i < 3; i++) {
        float4 a1 = k1[e * 24 + h * 3 + i];
        float4 b1 = q1[d * 24 + h * 3 + i];
        acc += a1.x * b1.x + a1.y * b1.y + a1.z * b1.z + a1.w * b1.w;
    }
    // score / sqrt(128); shift-free softmax is safe (|score| < ~3).
    g_ex[tid] = __expf(acc * 0.08838834764831845f);
    if (h == 0) atomicAdd(&g_count[d], 1);
}

// Phase 2a: single-block exclusive scan of g_count -> g_start/g_cursor.
__global__ void __launch_bounds__(1024) scan_kernel(int n)
{
    __shared__ int partials[1024];
    int t = threadIdx.x;
    int ch = (n + 1023) / 1024;
    int base = t * ch;
    int s = 0;
    for (int i = 0; i < ch; i++) {
        int idx = base + i;
        if (idx < n) s += g_count[idx];
    }
    partials[t] = s;
    __syncthreads();
    for (int off = 1; off < 1024; off <<= 1) {
        int v = (t >= off) ? partials[t - off] : 0;
        __syncthreads();
        partials[t] += v;
        __syncthreads();
    }
    int run = partials[t] - s;   // exclusive base for this chunk
    for (int i = 0; i < ch; i++) {
        int idx = base + i;
        if (idx < n) {
            g_start[idx]  = run;
            g_cursor[idx] = run;
            run += g_count[idx];
        }
    }
}

// Phase 2b: fill CSR buckets.
__global__ void __launch_bounds__(256) bin_kernel(
    const int* __restrict__ edge_dst, int E)
{
    int e = blockIdx.x * blockDim.x + threadIdx.x;
    if (e >= E) return;
    int d = load_dst(edge_dst, e);
    int slot = atomicAdd(&g_cursor[d], 1);
    g_bucket[slot] = e;
}

// Phase 3: warp per node. Lane mapping over the node's 32 output float4s:
//   lane 0..7   -> out0 float4 #lane      (head = lane)
//   lane 8..31  -> out1 float4 #(lane-8)  (head = (lane-8)/3)
// Per edge: uniform bucket load, ex load (one 32B sector, broadcast-dedup),
// v float4 (full-line), FMA. Unrolled x4 for MLP. Denominator accumulates in
// a register per lane (its own head) -> normalization is a local divide.
__global__ void __launch_bounds__(256) ga_gather_kernel(
    const float4* __restrict__ v0,   // [E*8]
    const float4* __restrict__ v1,   // [E*24]
    float* __restrict__ out,
    int n_nodes)
{
    int warp_id = (blockIdx.x * blockDim.x + threadIdx.x) >> 5;
    if (warp_id >= n_nodes) return;
    int lane = threadIdx.x & 31;
    int n = warp_id;

    bool lo = lane < 8;
    int j = lane - 8;                 // out1 float4 index (valid when !lo)
    int h = lo ? lane : j / 3;        // head owning this lane

    int start = g_start[n];
    int cnt   = g_count[n];

    float4 acc = make_float4(0.f, 0.f, 0.f, 0.f);
    float den = 0.f;

    int i = 0;
    for (; i + 4 <= cnt; i += 4) {
        int e0 = g_bucket[start + i + 0];
        int e1 = g_bucket[start + i + 1];
        int e2 = g_bucket[start + i + 2];
        int e3 = g_bucket[start + i + 3];

        float x0 = g_ex[e0 * 8 + h];
        float x1 = g_ex[e1 * 8 + h];
        float x2 = g_ex[e2 * 8 + h];
        float x3 = g_ex[e3 * 8 + h];

        float4 w0 = lo ? v0[e0 * 8 + lane] : v1[e0 * 24 + j];
        float4 w1 = lo ? v0[e1 * 8 + lane] : v1[e1 * 24 + j];
        float4 w2 = lo ? v0[e2 * 8 + lane] : v1[e2 * 24 + j];
        float4 w3 = lo ? v0[e3 * 8 + lane] : v1[e3 * 24 + j];

        den += (x0 + x1) + (x2 + x3);
        acc.x += x0 * w0.x; acc.y += x0 * w0.y; acc.z += x0 * w0.z; acc.w += x0 * w0.w;
        acc.x += x1 * w1.x; acc.y += x1 * w1.y; acc.z += x1 * w1.z; acc.w += x1 * w1.w;
        acc.x += x2 * w2.x; acc.y += x2 * w2.y; acc.z += x2 * w2.z; acc.w += x2 * w2.w;
        acc.x += x3 * w3.x; acc.y += x3 * w3.y; acc.z += x3 * w3.z; acc.w += x3 * w3.w;
    }
    for (; i < cnt; i++) {
        int e = g_bucket[start + i];
        float x = g_ex[e * 8 + h];
        float4 w = lo ? v0[e * 8 + lane] : v1[e * 24 + j];
        den += x;
        acc.x += x * w.x; acc.y += x * w.y; acc.z += x * w.z; acc.w += x * w.w;
    }

    float inv = (cnt > 0) ? (1.0f / den) : 0.0f;
    acc.x *= inv; acc.y *= inv; acc.z *= inv; acc.w *= inv;

    float* o = lo ? (out + (size_t)n * 32 + lane * 4)
                  : (out + (size_t)n_nodes * 32 + (size_t)n * 96 + j * 4);
    *(float4*)o = acc;
}

extern "C" void kernel_launch(void* const* d_in, const int* in_sizes, int n_in,
                              void* d_out, int out_size)
{
    const float4* q0 = (const float4*)d_in[0];
    const float4* q1 = (const float4*)d_in[1];
    const float4* k0 = (const float4*)d_in[2];
    const float4* k1 = (const float4*)d_in[3];
    const float4* v0 = (const float4*)d_in[4];
    const float4* v1 = (const float4*)d_in[5];
    const int* edge_dst = (const int*)d_in[6];
    float* out = (float*)d_out;

    int E = in_sizes[2] / 32;          // k0 has E*32 elements
    int n_nodes = out_size / 128;      // 32 + 96 floats per node

    void* cnt_ptr = nullptr;
    cudaGetSymbolAddress(&cnt_ptr, g_count);
    cudaMemsetAsync(cnt_ptr, 0, (size_t)n_nodes * sizeof(int));

    int total = E * N_HEADS_C;
    ga_score_kernel<<<(total + 255) / 256, 256>>>(k0, k1, q0, q1, edge_dst, E);

    scan_kernel<<<1, 1024>>>(n_nodes);

    int eb = (E + 255) / 256;
    bin_kernel<<<eb, 256>>>(edge_dst, E);

    int threads = n_nodes * 32;
    ga_gather_kernel<<<(threads + 255) / 256, 256>>>(v0, v1, out, n_nodes);
}

// round 6
// speedup vs baseline: 1.6074x; 1.3524x over previous
#include <cuda_runtime.h>
#include <cuda_bf16.h>

// GraphAttention, CSR-gather pipeline:
//   hist -> 3-stage multi-block scan -> score(+bin) -> warp-per-node gather.
// R5 post-mortem: single-block scan burned ~50us on one SM; gather at 68%
// DRAM was fine. This round: parallel scan, bin fused into score, gather
// unrolled x8 for more MLP.
//
// Inputs (metadata order): q0[N,32,1] q1[N,32,3] k0[E,32,1] k1[E,32,3]
//                          v0[E,32,1] v1[E,32,3] edge_dst[E] (int32 or int64)
// Output: concat(out0[N,32], out1[N,96]) float32, N*128 elements.

#define N_NODES_MAX 50176           // multiple of 256
#define NB_MAX      (N_NODES_MAX / 256)
#define E_MAX_C     800000
#define N_HEADS_C   8

__device__ float g_ex    [E_MAX_C * N_HEADS_C];
__device__ int   g_count [N_NODES_MAX];
__device__ int   g_start [N_NODES_MAX];
__device__ int   g_cursor[N_NODES_MAX];
__device__ int   g_bucket[E_MAX_C];
__device__ int   g_bsum  [NB_MAX];
__device__ int   g_boff  [NB_MAX];

// JAX with x64 disabled hands us int32 even though the reference asked for
// int64. Sniff dtype: for int64 the odd 32-bit words (high halves of indices
// < 50000) are all zero; for random int32 indices P(all four zero) ~ 0.
__device__ __forceinline__ int load_dst(const int* __restrict__ dst32, int e) {
    bool is64 = (dst32[1] == 0) & (dst32[3] == 0) & (dst32[5] == 0) & (dst32[7] == 0);
    return is64 ? dst32[2 * e] : dst32[e];
}

__global__ void __launch_bounds__(256) hist_kernel(
    const int* __restrict__ edge_dst, int E)
{
    int e = blockIdx.x * blockDim.x + threadIdx.x;
    if (e >= E) return;
    atomicAdd(&g_count[load_dst(edge_dst, e)], 1);
}

// Stage 1: block-local exclusive scan of 256 counts; block total -> g_bsum.
__global__ void __launch_bounds__(256) scan1_kernel(int n)
{
    __shared__ int sh[256];
    int t = threadIdx.x;
    int idx = blockIdx.x * 256 + t;
    int c = (idx < n) ? g_count[idx] : 0;
    sh[t] = c;
    __syncthreads();
#pragma unroll
    for (int off = 1; off < 256; off <<= 1) {
        int v = (t >= off) ? sh[t - off] : 0;
        __syncthreads();
        sh[t] += v;
        __syncthreads();
    }
    if (idx < n) g_start[idx] = sh[t] - c;      // exclusive within block
    if (t == 255) g_bsum[blockIdx.x] = sh[255]; // block total
}

// Stage 2: one block scans the (<=196) block totals -> exclusive offsets.
__global__ void __launch_bounds__(256) scan2_kernel(int nb)
{
    __shared__ int sh[256];
    int t = threadIdx.x;
    int c = (t < nb) ? g_bsum[t] : 0;
    sh[t] = c;
    __syncthreads();
#pragma unroll
    for (int off = 1; off < 256; off <<= 1) {
        int v = (t >= off) ? sh[t - off] : 0;
        __syncthreads();
        sh[t] += v;
        __syncthreads();
    }
    if (t < nb) g_boff[t] = sh[t] - c;
}

// Stage 3: add block offsets; init cursor.
__global__ void __launch_bounds__(256) scan3_kernel(int n)
{
    int idx = blockIdx.x * 256 + threadIdx.x;
    if (idx >= n) return;
    int s = g_start[idx] + g_boff[blockIdx.x];
    g_start[idx]  = s;
    g_cursor[idx] = s;
}

// Score(+bin): thread per (edge, head). Coalesced k stream, L2-resident q
// gather, 16 FMAs, exp, coalesced ex store. h==0 thread claims the CSR slot.
__global__ void __launch_bounds__(256) ga_score_kernel(
    const float4* __restrict__ k0,   // [E*8]  float4 view of [E,32]
    const float4* __restrict__ k1,   // [E*24] float4 view of [E,96]
    const float4* __restrict__ q0,   // [N*8]
    const float4* __restrict__ q1,   // [N*24]
    const int* __restrict__ edge_dst,
    int E)
{
    int tid = blockIdx.x * blockDim.x + threadIdx.x;
    if (tid >= E * N_HEADS_C) return;
    int e = tid >> 3;
    int h = tid & 7;
    int d = load_dst(edge_dst, e);

    float4 a0 = k0[e * 8 + h];
    float4 b0 = q0[d * 8 + h];
    float acc = a0.x * b0.x + a0.y * b0.y + a0.z * b0.z + a0.w * b0.w;
#pragma unroll
    for (int i = 0; i < 3; i++) {
        float4 a1 = k1[e * 24 + h * 3 + i];
        float4 b1 = q1[d * 24 + h * 3 + i];
        acc += a1.x * b1.x + a1.y * b1.y + a1.z * b1.z + a1.w * b1.w;
    }
    // score / sqrt(128); shift-free softmax is safe (|score| < ~3).
    g_ex[tid] = __expf(acc * 0.08838834764831845f);
    if (h == 0) {
        int slot = atomicAdd(&g_cursor[d], 1);
        g_bucket[slot] = e;
    }
}

// Gather: warp per node. Lane mapping over the node's 32 output float4s:
//   lane 0..7   -> out0 float4 #lane      (head = lane)
//   lane 8..31  -> out1 float4 #(lane-8)  (head = (lane-8)/3)
// Unrolled x8 for MLP; per-lane denominator for its own head -> local divide.
__global__ void __launch_bounds__(256) ga_gather_kernel(
    const float4* __restrict__ v0,   // [E*8]
    const float4* __restrict__ v1,   // [E*24]
    float* __restrict__ out,
    int n_nodes)
{
    int warp_id = (blockIdx.x * blockDim.x + threadIdx.x) >> 5;
    if (warp_id >= n_nodes) return;
    int lane = threadIdx.x & 31;
    int n = warp_id;

    bool lo = lane < 8;
    int j = lane - 8;                 // out1 float4 index (valid when !lo)
    int h = lo ? lane : j / 3;        // head owning this lane

    int start = g_start[n];
    int cnt   = g_count[n];

    float4 acc = make_float4(0.f, 0.f, 0.f, 0.f);
    float den = 0.f;

    int i = 0;
    for (; i + 8 <= cnt; i += 8) {
        int   eid[8];
        float x[8];
        float4 w[8];
#pragma unroll
        for (int u = 0; u < 8; u++) eid[u] = g_bucket[start + i + u];
#pragma unroll
        for (int u = 0; u < 8; u++) x[u] = g_ex[eid[u] * 8 + h];
#pragma unroll
        for (int u = 0; u < 8; u++)
            w[u] = lo ? v0[eid[u] * 8 + lane] : v1[eid[u] * 24 + j];
#pragma unroll
        for (int u = 0; u < 8; u++) {
            den  += x[u];
            acc.x += x[u] * w[u].x;
            acc.y += x[u] * w[u].y;
            acc.z += x[u] * w[u].z;
            acc.w += x[u] * w[u].w;
        }
    }
    for (; i < cnt; i++) {
        int e = g_bucket[start + i];
        float x = g_ex[e * 8 + h];
        float4 w = lo ? v0[e * 8 + lane] : v1[e * 24 + j];
        den += x;
        acc.x += x * w.x; acc.y += x * w.y; acc.z += x * w.z; acc.w += x * w.w;
    }

    float inv = (cnt > 0) ? (1.0f / den) : 0.0f;
    acc.x *= inv; acc.y *= inv; acc.z *= inv; acc.w *= inv;

    float* o = lo ? (out + (size_t)n * 32 + lane * 4)
                  : (out + (size_t)n_nodes * 32 + (size_t)n * 96 + j * 4);
    *(float4*)o = acc;
}

extern "C" void kernel_launch(void* const* d_in, const int* in_sizes, int n_in,
                              void* d_out, int out_size)
{
    const float4* q0 = (const float4*)d_in[0];
    const float4* q1 = (const float4*)d_in[1];
    const float4* k0 = (const float4*)d_in[2];
    const float4* k1 = (const float4*)d_in[3];
    const float4* v0 = (const float4*)d_in[4];
    const float4* v1 = (const float4*)d_in[5];
    const int* edge_dst = (const int*)d_in[6];
    float* out = (float*)d_out;

    int E = in_sizes[2] / 32;          // k0 has E*32 elements
    int n_nodes = out_size / 128;      // 32 + 96 floats per node

    void* cnt_ptr = nullptr;
    cudaGetSymbolAddress(&cnt_ptr, g_count);
    cudaMemsetAsync(cnt_ptr, 0, (size_t)n_nodes * sizeof(int));

    int eb = (E + 255) / 256;
    hist_kernel<<<eb, 256>>>(edge_dst, E);

    int nb = (n_nodes + 255) / 256;
    scan1_kernel<<<nb, 256>>>(n_nodes);
    scan2_kernel<<<1, 256>>>(nb);
    scan3_kernel<<<nb, 256>>>(n_nodes);

    int total = E * N_HEADS_C;
    ga_score_kernel<<<(total + 255) / 256, 256>>>(k0, k1, q0, q1, edge_dst, E);

    int threads = n_nodes * 32;
    ga_gather_kernel<<<(threads + 255) / 256, 256>>>(v0, v1, out, n_nodes);
}